// round 2
// baseline (speedup 1.0000x reference)
#include <cuda_runtime.h>
#include <math.h>
#include <stdint.h>

#define DZ 64
#define DC 32
#define TILE 128
#define THREADS 128

// Packed f32x2 FMA (Blackwell FFMA2): d = a*b + d on two packed floats.
#define FMA_F32X2(acc, a, b) \
    asm("fma.rn.f32x2 %0, %1, %2, %0;" : "+l"(acc) : "l"(a), "l"(b))

__global__ __launch_bounds__(THREADS)
void dec_cat_kernel(const float* __restrict__ Z,
                    const float* __restrict__ beta,
                    float* __restrict__ out,
                    int T)
{
    // Z tile: stride 65 -> conflict-free scalar reads (bank = (tid + d) mod 32)
    __shared__ float zs[TILE][DZ + 1];
    // beta transposed, d-major: bs[d][c]; row = 128B (16B-aligned for ulonglong2)
    __shared__ float bs[DZ][DC];

    const int tid = threadIdx.x;
    const int rowBase = blockIdx.x * TILE;
    const int rowsHere = min(TILE, T - rowBase);

    // ---- load beta (transpose, zero the unused last channel row) ----
    for (int i = tid; i < DC * DZ; i += THREADS) {
        int c = i >> 6;      // channel
        int d = i & 63;      // feature
        float v = (c == DC - 1) ? 0.0f : beta[i];
        bs[d][c] = v;
    }

    // ---- load Z tile, coalesced float4 reads, scalar smem stores ----
    {
        const float4* Z4 = reinterpret_cast<const float4*>(Z + (size_t)rowBase * DZ);
        const int n4 = rowsHere * (DZ / 4);
        for (int i = tid; i < n4; i += THREADS) {
            float4 v = Z4[i];
            int r = i >> 4;          // 16 float4 per row
            int k = (i & 15) << 2;   // feature base
            zs[r][k + 0] = v.x;
            zs[r][k + 1] = v.y;
            zs[r][k + 2] = v.z;
            zs[r][k + 3] = v.w;
        }
    }
    __syncthreads();

    const int row = tid;
    if (row >= rowsHere) return;

    // ---- main loop: 16 packed f32x2 accumulators = 32 channel logits ----
    unsigned long long acc[16];
#pragma unroll
    for (int j = 0; j < 16; j++) acc[j] = 0ull;   // (+0, +0)

    const ulonglong2* bp = reinterpret_cast<const ulonglong2*>(&bs[0][0]);

#pragma unroll 8
    for (int d = 0; d < DZ; d++) {
        float zd = zs[row][d];
        unsigned long long z2;
        asm("mov.b64 %0, {%1, %1};" : "=l"(z2) : "f"(zd));
        const ulonglong2* b = bp + d * 8;   // 8 x 16B = 128B per d
#pragma unroll
        for (int j2 = 0; j2 < 8; j2++) {
            ulonglong2 bb = b[j2];
            FMA_F32X2(acc[2 * j2 + 0], z2, bb.x);
            FMA_F32X2(acc[2 * j2 + 1], z2, bb.y);
        }
    }

    // ---- unpack logits (l[31] == +0 exactly -> e = 1, the implicit channel) ----
    float l[DC];
#pragma unroll
    for (int j = 0; j < 16; j++) {
        asm("mov.b64 {%0, %1}, %2;" : "=f"(l[2 * j]), "=f"(l[2 * j + 1]) : "l"(acc[j]));
    }

    // ---- fast argmax over logits (exp and /norm are monotone) ----
    float m = l[0];
    int idx = 0;
#pragma unroll
    for (int c = 1; c < DC; c++) {
        if (l[c] > m) { m = l[c]; idx = c; }
    }

    // Rare path trigger: top-2 gap < 1e-6. Outside this window the result is
    // insensitive to accumulation-order noise (~3e-8), exp rounding (~1.2e-7
    // collapse) and prob-division rounding (~1.2e-7 relative collapse).
    const float th = m - 1e-6f;
    int cnt = 0;
#pragma unroll
    for (int c = 0; c < DC; c++) cnt += (l[c] >= th);

    if (cnt > 1) {
        // Rare path (~3e-5 of rows): emulate the reference pipeline with
        // minimum-variance arithmetic:
        //   logits: exact double accumulation, rounded to fp32
        //   e     : correctly-rounded fp32 exp via double exp (fast-math-immune)
        //   norm  : 1 + sequential fp32 sum of e
        //   probs : IEEE fp32 division (fast-math-immune)
        //   argmax: first-index tie semantics (strict >)
        float e[DC];
#pragma unroll 1
        for (int c = 0; c < DC - 1; c++) {
            double s = 0.0;
#pragma unroll 1
            for (int d = 0; d < DZ; d++)
                s += (double)zs[row][d] * (double)bs[d][c];
            float lf = (float)s;
            e[c] = (float)exp((double)lf);
        }
        e[DC - 1] = 1.0f;

        float se = e[0];
#pragma unroll 1
        for (int c = 1; c < DC - 1; c++) se += e[c];
        float norm = 1.0f + se;

        float pb = -1.0f;
        int bi = 0;
#pragma unroll 1
        for (int c = 0; c < DC; c++) {
            float p = __fdiv_rn(e[c], norm);
            if (p > pb) { pb = p; bi = c; }   // strict > keeps first index on ties
        }
        idx = bi;
    }

    // ---- one-hot write: 8 x STG.128 per row ----
    float4* o4 = reinterpret_cast<float4*>(out + (size_t)(rowBase + row) * DC);
#pragma unroll
    for (int q = 0; q < 8; q++) {
        int c0 = q << 2;
        float4 v;
        v.x = (idx == c0 + 0) ? 1.0f : 0.0f;
        v.y = (idx == c0 + 1) ? 1.0f : 0.0f;
        v.z = (idx == c0 + 2) ? 1.0f : 0.0f;
        v.w = (idx == c0 + 3) ? 1.0f : 0.0f;
        o4[q] = v;
    }
}

extern "C" void kernel_launch(void* const* d_in, const int* in_sizes, int n_in,
                              void* d_out, int out_size)
{
    const float* Z    = (const float*)d_in[0];
    const float* beta = (const float*)d_in[1];
    float* out        = (float*)d_out;

    const int T = in_sizes[0] / DZ;
    const int grid = (T + TILE - 1) / TILE;

    dec_cat_kernel<<<grid, THREADS>>>(Z, beta, out, T);
}

// round 3
// speedup vs baseline: 1.0243x; 1.0243x over previous
#include <cuda_runtime.h>
#include <math.h>
#include <stdint.h>

#define DZ 64
#define DC 32
#define TILE 128
#define THREADS 128
#define ROWS_PER_WARP 32

// Packed f32x2 ops (Blackwell FFMA2 path)
#define FMA_F32X2(acc, a, b) \
    asm("fma.rn.f32x2 %0, %1, %2, %0;" : "+l"(acc) : "l"(a), "l"(b))
#define ADD_F32X2(d, a, b) \
    asm("add.rn.f32x2 %0, %1, %2;" : "=l"(d) : "l"(a), "l"(b))

__global__ __launch_bounds__(THREADS, 4)
void dec_cat_kernel(const float* __restrict__ Z,
                    const float* __restrict__ beta,
                    float* __restrict__ out,
                    int T)
{
    // Z tile, no padding needed: compute reads are whole-warp broadcasts.
    __shared__ float zs[TILE][DZ];   // 32 KB

    const int tid  = threadIdx.x;
    const int lane = tid & 31;
    const int w    = tid >> 5;
    const int rowBase = blockIdx.x * TILE;
    const int rowsHere = min(TILE, T - rowBase);

    // ---- beta in registers: lane c holds channel c's 64 coeffs as 32 packed
    //      d-pairs (b[c][2j], b[c][2j+1]). Channel 31 (implicit) = zeros. ----
    unsigned long long br[DZ / 2];
    if (lane < DC - 1) {
        const ulonglong2* bp = reinterpret_cast<const ulonglong2*>(beta + lane * DZ);
#pragma unroll
        for (int q = 0; q < 16; q++) {
            ulonglong2 v = bp[q];
            br[2 * q]     = v.x;
            br[2 * q + 1] = v.y;
        }
    } else {
#pragma unroll
        for (int q = 0; q < DZ / 2; q++) br[q] = 0ull;
    }

    // ---- stage Z tile: coalesced float4 global loads -> smem ----
    {
        const float4* Z4 = reinterpret_cast<const float4*>(Z + (size_t)rowBase * DZ);
        const int n4 = rowsHere * (DZ / 4);
        float4* zs4 = reinterpret_cast<float4*>(&zs[0][0]);
        for (int i = tid; i < n4; i += THREADS) {
            zs4[i] = Z4[i];
        }
    }
    __syncthreads();

    // ---- each warp handles 32 consecutive rows of the tile ----
    const int rw0 = w * ROWS_PER_WARP;

#pragma unroll 1
    for (int i = 0; i < ROWS_PER_WARP; i++) {
        const int r = rw0 + i;
        if (r >= rowsHere) break;

        // z row, packed d-pairs, whole-warp broadcast reads (LDS.128)
        const ulonglong2* zp = reinterpret_cast<const ulonglong2*>(&zs[r][0]);

        unsigned long long a0 = 0ull, a1 = 0ull, a2 = 0ull, a3 = 0ull;
#pragma unroll
        for (int q = 0; q < 8; q++) {
            ulonglong2 u = zp[2 * q];
            ulonglong2 v = zp[2 * q + 1];
            FMA_F32X2(a0, u.x, br[4 * q + 0]);
            FMA_F32X2(a1, u.y, br[4 * q + 1]);
            FMA_F32X2(a2, v.x, br[4 * q + 2]);
            FMA_F32X2(a3, v.y, br[4 * q + 3]);
        }
        ADD_F32X2(a0, a0, a1);
        ADD_F32X2(a2, a2, a3);
        ADD_F32X2(a0, a0, a2);

        float lo, hi;
        asm("mov.b64 {%0, %1}, %2;" : "=f"(lo), "=f"(hi) : "l"(a0));
        const float l = lo + hi;         // lane c's logit; lane 31 -> +0 exactly

        // ---- warp argmax, first-index tie-break ----
        // orderable encoding: monotone bijection float -> uint
        unsigned u = __float_as_uint(l);
        u = (u & 0x80000000u) ? ~u : (u | 0x80000000u);
        unsigned umax;
        asm("redux.sync.max.u32 %0, %1, 0xffffffff;" : "=r"(umax) : "r"(u));
        const unsigned winMask = __ballot_sync(0xffffffffu, u == umax);
        int idx = __ffs(winMask) - 1;    // lowest channel among exact maxima

        // ---- rare-path trigger: top-2 gap < 1e-6 (decision-risk window ~4e-7) ----
        const float m = (umax & 0x80000000u) ? __uint_as_float(umax ^ 0x80000000u)
                                             : __uint_as_float(~umax);
        const unsigned nearMask = __ballot_sync(0xffffffffu, l >= m - 1e-6f);

        if (__popc(nearMask) > 1) {
            // Rare (~3e-5 of rows): emulate the reference pipeline exactly.
            //   logits: exact double accumulation -> fp32
            //   e     : correctly-rounded fp32 exp (via double exp)
            //   norm  : 1 + sequential fp32 sum
            //   probs : IEEE fp32 division
            //   argmax: first-index tie semantics
            int bi = 0;
            if (lane == 0) {
                float e[DC];
#pragma unroll 1
                for (int c = 0; c < DC - 1; c++) {
                    double s = 0.0;
#pragma unroll 1
                    for (int d = 0; d < DZ; d++)
                        s += (double)zs[r][d] * (double)beta[c * DZ + d];
                    float lf = (float)s;
                    e[c] = (float)exp((double)lf);
                }
                e[DC - 1] = 1.0f;
                float se = e[0];
#pragma unroll 1
                for (int c = 1; c < DC - 1; c++) se += e[c];
                const float norm = 1.0f + se;
                float pb = -1.0f;
#pragma unroll 1
                for (int c = 0; c < DC; c++) {
                    float p = __fdiv_rn(e[c], norm);
                    if (p > pb) { pb = p; bi = c; }  // strict > keeps first index
                }
            }
            idx = __shfl_sync(0xffffffffu, bi, 0);
        }

        // ---- one-hot: one coalesced 128B store per row (STG.32 per lane) ----
        out[(size_t)(rowBase + r) * DC + lane] = (lane == idx) ? 1.0f : 0.0f;
    }
}

extern "C" void kernel_launch(void* const* d_in, const int* in_sizes, int n_in,
                              void* d_out, int out_size)
{
    const float* Z    = (const float*)d_in[0];
    const float* beta = (const float*)d_in[1];
    float* out        = (float*)d_out;

    const int T = in_sizes[0] / DZ;
    const int grid = (T + TILE - 1) / TILE;

    dec_cat_kernel<<<grid, THREADS>>>(Z, beta, out, T);
}